// round 12
// baseline (speedup 1.0000x reference)
#include <cuda_runtime.h>
#include <cstdint>

// ---------------------------------------------------------------------------
// Problem constants
// ---------------------------------------------------------------------------
#define BSZ   8192
#define MT    256           // batch rows per job tile
#define THR   256
#define NJOBS 2048          // 64 blocks x 32 tiles
#define NCTA  148

// ---------------------------------------------------------------------------
// Device scratch (allocation-free rule: __device__ globals)
// ---------------------------------------------------------------------------
// Exchange: g_S[(d*64 + m)][b]  (layer-0 block m, out-dim d, batch b).
__device__ __align__(256) float g_S [(size_t)4096 * BSZ];
__device__ __align__(256) float g_S2[(size_t)4096 * BSZ];      // [f][b] -> transpose

// ---------------------------------------------------------------------------
// SMEM layout (float offsets)
// ---------------------------------------------------------------------------
#define PAB   68            // layer0: sA [b=256][k=64]  pitch 68  (frag bank 4g+tig)
#define PAK   264           // layer1: sA [k=64][b=256]  pitch 264 (frag bank 8tig+g)
#define ABUF  17408         // floats per A buffer (max of both layouts)
#define PW1P  132           // sW1p [p=32][e=128] float2 pitch (bank 4tig+g CF)
#define PW2P  68            // sW2p [p=64][d=64]  float2 pitch (bank 4tig+g CF)

#define OFF_A0   0
#define OFF_A1   ABUF
#define OFF_W1   (2 * ABUF)                 // 8448 floats
#define OFF_W2   (OFF_W1 + 32 * PW1P * 2)   // 8704 floats
#define OFF_B1   (OFF_W2 + 64 * PW2P * 2)
#define OFF_B2   (OFF_B1 + 128)
#define SMEM_FLOATS (OFF_B2 + 64)
#define SMEM_BYTES  (SMEM_FLOATS * 4)       // 208,640 B -> 1 CTA/SM

// ---------------------------------------------------------------------------
// Helpers (no sm_103a-only instructions)
// ---------------------------------------------------------------------------
static __device__ __forceinline__ uint32_t smem_u32(const void* p) {
    uint32_t a;
    asm("{ .reg .u64 t; cvta.to.shared.u64 t, %1; cvt.u32.u64 %0, t; }" : "=r"(a) : "l"(p));
    return a;
}
static __device__ __forceinline__ uint32_t f2tf(float f) {
    uint32_t u;
    asm("cvt.rna.tf32.f32 %0, %1;" : "=r"(u) : "f"(f));
    return u;
}
static __device__ __forceinline__ float rna_tf32(float f) {
    return __uint_as_float(f2tf(f));
}
static __device__ __forceinline__ void mma8(float* d, const uint32_t* a,
                                            uint32_t b0, uint32_t b1) {
    asm volatile(
        "mma.sync.aligned.m16n8k8.row.col.f32.tf32.tf32.f32 "
        "{%0,%1,%2,%3},{%4,%5,%6,%7},{%8,%9},{%0,%1,%2,%3};"
        : "+f"(d[0]), "+f"(d[1]), "+f"(d[2]), "+f"(d[3])
        : "r"(a[0]), "r"(a[1]), "r"(a[2]), "r"(a[3]), "r"(b0), "r"(b1));
}
#define CP16(dst, src) \
    asm volatile("cp.async.cg.shared.global [%0], [%1], 16;" :: "r"(dst), "l"(src))
#define CP_COMMIT() asm volatile("cp.async.commit_group;" ::: "memory")
#define CP_WAIT0()  asm volatile("cp.async.wait_group 0;" ::: "memory")
#define CP_WAIT1()  asm volatile("cp.async.wait_group 1;" ::: "memory")

// ---------------------------------------------------------------------------
// A-tile prefetch via cp.async (raw copy; tf32 rounding at fragment load)
// ---------------------------------------------------------------------------
template <int LAYER>
static __device__ __forceinline__ void prefetchA(uint32_t sbuf, int j, int t,
                                                 const float* __restrict__ x) {
    const int blk = j >> 5;
    const int b0  = (j & 31) * MT;
    if (LAYER == 0) {
#pragma unroll
        for (int i = 0; i < 16; i++) {
            int idx = i * THR + t;          // 4096 float4 = 256 b x 16 k4
            int b = idx >> 4, k4 = idx & 15;
            const float* src = x + (size_t)(b0 + b) * 4096 + blk * 64 + k4 * 4;
            CP16(sbuf + (uint32_t)(b * PAB + k4 * 4) * 4u, src);
        }
    } else {
#pragma unroll
        for (int i = 0; i < 16; i++) {
            int idx = i * THR + t;          // 4096 float4 = 64 k x 64 b4
            int k = idx >> 6, b4 = idx & 63;
            const float* src = g_S + ((size_t)blk * 64 + k) * BSZ + b0 + b4 * 4;
            CP16(sbuf + (uint32_t)(k * PAK + b4 * 4) * 4u, src);
        }
    }
}

// ---------------------------------------------------------------------------
// Persistent layer kernel. Grid: 148 CTAs, 256 threads, 8 warps.
// Each CTA owns a contiguous job range; weights reloaded only on blk change;
// A-tiles double-buffered with cp.async overlap.
// ---------------------------------------------------------------------------
template <int LAYER>
__global__ void __launch_bounds__(THR, 1)
layer_kernel(const float* __restrict__ x,
             const float* __restrict__ w1g, const float* __restrict__ b1g,
             const float* __restrict__ w2g, const float* __restrict__ b2g) {
    extern __shared__ float sm[];
    float2* sW1p = (float2*)(sm + OFF_W1);
    float2* sW2p = (float2*)(sm + OFF_W2);
    float*  sb1  = sm + OFF_B1;
    float*  sb2  = sm + OFF_B2;
    const uint32_t sA0u = smem_u32(sm + OFF_A0);
    const uint32_t sA1u = smem_u32(sm + OFF_A1);

    const int t    = threadIdx.x;
    const int wid  = t >> 5;
    const int lane = t & 31;
    const int g    = lane >> 2;
    const int tig  = lane & 3;

    const int c     = blockIdx.x;
    const int start = (NJOBS * c) / NCTA;
    const int end   = (NJOBS * (c + 1)) / NCTA;

    const int m0  = wid * 32;
    const int r0a = m0 + g;
    const int r0b = m0 + 16 + g;
    const int qbase = lane & ~3;
    const int s0 = qbase | (tig >> 1);
    const int s2 = s0 | 2;
    const bool odd = (tig & 1);

    // prologue: prefetch first job's A into buf0
    prefetchA<LAYER>(sA0u, start, t, x);
    CP_COMMIT();

    int curblk = -1;
#pragma unroll 1
    for (int j = start; j < end; j++) {
        const int p   = (j - start) & 1;
        const int blk = j >> 5;
        const int b0  = (j & 31) * MT;

        // ---- weights + biases on segment change (after prev-iter barrier)
        if (blk != curblk) {
            curblk = blk;
            const int ln = LAYER * 64 + blk;
            if (t < 128)      sb1[t]       = b1g[(size_t)ln * 128 + t];
            else if (t < 192) sb2[t - 128] = b2g[(size_t)ln * 64 + (t - 128)];
            {
                const float4* src = (const float4*)(w1g + (size_t)ln * 8192);
#pragma unroll
                for (int i = 0; i < 4; i++) {
                    int idx = i * THR + t;  // 1024 = 32 p x 32 e4
                    int pp = idx >> 5, e4 = idx & 31;
                    int klo = (pp >> 2) * 8 + (pp & 3);
                    float4 vlo = src[klo * 32 + e4];
                    float4 vhi = src[(klo + 4) * 32 + e4];
                    float2* dst = sW1p + pp * PW1P + e4 * 4;
                    dst[0] = make_float2(rna_tf32(vlo.x), rna_tf32(vhi.x));
                    dst[1] = make_float2(rna_tf32(vlo.y), rna_tf32(vhi.y));
                    dst[2] = make_float2(rna_tf32(vlo.z), rna_tf32(vhi.z));
                    dst[3] = make_float2(rna_tf32(vlo.w), rna_tf32(vhi.w));
                }
            }
            {
                const float4* src = (const float4*)(w2g + (size_t)ln * 8192);
#pragma unroll
                for (int i = 0; i < 4; i++) {
                    int idx = i * THR + t;  // 1024 = 64 p x 16 d4
                    int pp = idx >> 4, d4 = idx & 15;
                    int klo = (pp >> 2) * 8 + (pp & 3);
                    float4 vlo = src[klo * 16 + d4];
                    float4 vhi = src[(klo + 4) * 16 + d4];
                    float2* dst = sW2p + pp * PW2P + d4 * 4;
                    dst[0] = make_float2(rna_tf32(vlo.x), rna_tf32(vhi.x));
                    dst[1] = make_float2(rna_tf32(vlo.y), rna_tf32(vhi.y));
                    dst[2] = make_float2(rna_tf32(vlo.z), rna_tf32(vhi.z));
                    dst[3] = make_float2(rna_tf32(vlo.w), rna_tf32(vhi.w));
                }
            }
        }

        // ---- prefetch next job's A into the other buffer (overlaps compute)
        const bool hasnext = (j + 1 < end);
        if (hasnext) {
            prefetchA<LAYER>(p ? sA0u : sA1u, j + 1, t, x);
            CP_COMMIT();
        }
        if (hasnext) CP_WAIT1(); else CP_WAIT0();
        __syncthreads();                    // A(cur) + W visible to all warps

        const float* sA = p ? (sm + OFF_A1) : (sm + OFF_A0);

        // ---- GEMM1 A-fragments (rounded once)
        uint32_t au[2][8][4];
#pragma unroll
        for (int kt = 0; kt < 8; kt++) {
            int k = kt * 8 + tig;
            if (LAYER == 0) {
                au[0][kt][0] = f2tf(sA[r0a * PAB + k]);
                au[0][kt][1] = f2tf(sA[(r0a + 8) * PAB + k]);
                au[0][kt][2] = f2tf(sA[r0a * PAB + k + 4]);
                au[0][kt][3] = f2tf(sA[(r0a + 8) * PAB + k + 4]);
                au[1][kt][0] = f2tf(sA[r0b * PAB + k]);
                au[1][kt][1] = f2tf(sA[(r0b + 8) * PAB + k]);
                au[1][kt][2] = f2tf(sA[r0b * PAB + k + 4]);
                au[1][kt][3] = f2tf(sA[(r0b + 8) * PAB + k + 4]);
            } else {
                au[0][kt][0] = f2tf(sA[k * PAK + r0a]);
                au[0][kt][1] = f2tf(sA[k * PAK + r0a + 8]);
                au[0][kt][2] = f2tf(sA[(k + 4) * PAK + r0a]);
                au[0][kt][3] = f2tf(sA[(k + 4) * PAK + r0a + 8]);
                au[1][kt][0] = f2tf(sA[k * PAK + r0b]);
                au[1][kt][1] = f2tf(sA[k * PAK + r0b + 8]);
                au[1][kt][2] = f2tf(sA[(k + 4) * PAK + r0b]);
                au[1][kt][3] = f2tf(sA[(k + 4) * PAK + r0b + 8]);
            }
        }

        // ---- fused GEMM1 -> ELU -> GEMM2 over 16 e-blocks
        float acc2[2][8][4];
#pragma unroll
        for (int mt = 0; mt < 2; mt++)
#pragma unroll
            for (int nt = 0; nt < 8; nt++)
#pragma unroll
                for (int cc = 0; cc < 4; cc++) acc2[mt][nt][cc] = 0.f;

#pragma unroll
        for (int kb = 0; kb < 16; kb++) {
            float a1[2][4] = {{0.f, 0.f, 0.f, 0.f}, {0.f, 0.f, 0.f, 0.f}};
#pragma unroll
            for (int kt = 0; kt < 8; kt++) {
                float2 w = sW1p[(kt * 4 + tig) * PW1P + kb * 8 + g];
                uint32_t w0 = __float_as_uint(w.x), w1v = __float_as_uint(w.y);
                mma8(a1[0], au[0][kt], w0, w1v);
                mma8(a1[1], au[1][kt], w0, w1v);
            }

            float bb0 = sb1[kb * 8 + tig * 2];
            float bb1 = sb1[kb * 8 + tig * 2 + 1];
            uint32_t a2f[2][4];
#pragma unroll
            for (int mt = 0; mt < 2; mt++) {
                float h0 = a1[mt][0] + bb0;
                float h1 = a1[mt][1] + bb1;
                float h2 = a1[mt][2] + bb0;
                float h3 = a1[mt][3] + bb1;
                h0 = rna_tf32(h0 > 0.f ? h0 : (__expf(h0) - 1.f));
                h1 = rna_tf32(h1 > 0.f ? h1 : (__expf(h1) - 1.f));
                h2 = rna_tf32(h2 > 0.f ? h2 : (__expf(h2) - 1.f));
                h3 = rna_tf32(h3 > 0.f ? h3 : (__expf(h3) - 1.f));

                float p0 = __shfl_sync(0xffffffffu, h0, s0);
                float p1 = __shfl_sync(0xffffffffu, h1, s0);
                float q0 = __shfl_sync(0xffffffffu, h2, s0);
                float q1 = __shfl_sync(0xffffffffu, h3, s0);
                float r0f = __shfl_sync(0xffffffffu, h0, s2);
                float r1f = __shfl_sync(0xffffffffu, h1, s2);
                float u0 = __shfl_sync(0xffffffffu, h2, s2);
                float u1 = __shfl_sync(0xffffffffu, h3, s2);
                a2f[mt][0] = __float_as_uint(odd ? p1 : p0);
                a2f[mt][1] = __float_as_uint(odd ? q1 : q0);
                a2f[mt][2] = __float_as_uint(odd ? r1f : r0f);
                a2f[mt][3] = __float_as_uint(odd ? u1 : u0);
            }

#pragma unroll
            for (int nt = 0; nt < 8; nt++) {
                float2 w = sW2p[(kb * 4 + tig) * PW2P + nt * 8 + g];
                uint32_t w0 = __float_as_uint(w.x), w1v = __float_as_uint(w.y);
                mma8(acc2[0][nt], a2f[0], w0, w1v);
                mma8(acc2[1][nt], a2f[1], w0, w1v);
            }
        }

        // ---- epilogue: bias + residual (exact z from sA) + stores
#pragma unroll
        for (int mt = 0; mt < 2; mt++) {
            const int rbase = m0 + mt * 16 + g;
#pragma unroll
            for (int nt = 0; nt < 8; nt++) {
#pragma unroll
                for (int cc = 0; cc < 4; cc++) {
                    int row = rbase + 8 * (cc >> 1);
                    int d   = nt * 8 + tig * 2 + (cc & 1);
                    float z = (LAYER == 0) ? sA[row * PAB + d] : sA[d * PAK + row];
                    float v = acc2[mt][nt][cc] + sb2[d] + z;
                    if (LAYER == 0)
                        g_S [((size_t)d * 64 + blk) * BSZ + b0 + row] = v;
                    else
                        g_S2[((size_t)d * 64 + blk) * BSZ + b0 + row] = v;
                }
            }
        }
        __syncthreads();                    // protect sA(cur) + sW before reuse
    }
}

// ---------------------------------------------------------------------------
// Final transpose: out[b][f] = g_S2[f][b]   (4096 x 8192 -> 8192 x 4096)
// ---------------------------------------------------------------------------
__global__ void __launch_bounds__(256)
transpose_kernel(float* __restrict__ out) {
    __shared__ float tile[64 * 68];
    const int f0 = blockIdx.x * 64, bb0 = blockIdx.y * 64;
    const int t = threadIdx.x;
#pragma unroll
    for (int p = 0; p < 4; p++) {
        int idx = p * 256 + t;
        int f = idx >> 4, b4 = idx & 15;
        float4 v = *(const float4*)(g_S2 + (size_t)(f0 + f) * BSZ + bb0 + b4 * 4);
        float* d = tile + f * 68 + b4 * 4;
        d[0] = v.x; d[1] = v.y; d[2] = v.z; d[3] = v.w;
    }
    __syncthreads();
#pragma unroll
    for (int p = 0; p < 4; p++) {
        int idx = p * 256 + t;
        int b = idx >> 4, f4 = idx & 15;
        float4 v;
        v.x = tile[(f4 * 4 + 0) * 68 + b];
        v.y = tile[(f4 * 4 + 1) * 68 + b];
        v.z = tile[(f4 * 4 + 2) * 68 + b];
        v.w = tile[(f4 * 4 + 3) * 68 + b];
        *(float4*)(out + (size_t)(bb0 + b) * 4096 + f0 + f4 * 4) = v;
    }
}

// ---------------------------------------------------------------------------
// kernel_launch
// ---------------------------------------------------------------------------
extern "C" void kernel_launch(void* const* d_in, const int* in_sizes, int n_in,
                              void* d_out, int out_size) {
    const float* x  = (const float*)d_in[0];
    const float* w1 = (const float*)d_in[1];
    const float* b1 = (const float*)d_in[2];
    const float* w2 = (const float*)d_in[3];
    const float* b2 = (const float*)d_in[4];
    float* out = (float*)d_out;
    (void)in_sizes; (void)n_in; (void)out_size;

    cudaFuncSetAttribute(layer_kernel<0>, cudaFuncAttributeMaxDynamicSharedMemorySize, SMEM_BYTES);
    cudaFuncSetAttribute(layer_kernel<1>, cudaFuncAttributeMaxDynamicSharedMemorySize, SMEM_BYTES);

    layer_kernel<0><<<NCTA, THR, SMEM_BYTES>>>(x, w1, b1, w2, b2);
    layer_kernel<1><<<NCTA, THR, SMEM_BYTES>>>(x, w1, b1, w2, b2);
    transpose_kernel<<<dim3(64, 128), 256>>>(out);
}

// round 13
// speedup vs baseline: 1.1001x; 1.1001x over previous
#include <cuda_runtime.h>
#include <cstdint>

// ---------------------------------------------------------------------------
// Problem constants
// ---------------------------------------------------------------------------
#define BSZ   8192
#define MT    256           // batch rows per CTA tile
#define THR   256

// ---------------------------------------------------------------------------
// Device scratch (allocation-free rule: __device__ globals)
// ---------------------------------------------------------------------------
// Exchange: g_S[(d*64 + m)][b]  (layer-0 block m, out-dim d, batch b).
// Layer-1 block n reads rows (n*64 + c), c=0..63 -> contiguous in b.
__device__ __align__(256) float g_S [(size_t)4096 * BSZ];
__device__ __align__(256) float g_S2[(size_t)4096 * BSZ];      // [f][b] -> transpose

// ---------------------------------------------------------------------------
// SMEM layout (float offsets)
// ---------------------------------------------------------------------------
#define PAB   68            // layer0: sA [b=256][k=64]  pitch 68  (frag bank 4g+tig)
#define PAK   264           // layer1: sA [k=64][b=256]  pitch 264 (frag bank 8tig+g)
#define PW1P  132           // sW1p [p=32][e=128] float2, pitch 132 f2 (bank 8tig+2g CF)
#define PW2P  68            // sW2p [p=64][d=64]  float2, pitch 68 f2

#define OFF_A    0                          // max(256*68, 64*264) = 17408 floats
#define OFF_W1   17408                      // 32*132 f2 = 8448 floats
#define OFF_W2   (OFF_W1 + 32 * PW1P * 2)   // 64*68 f2  = 8704 floats
#define OFF_B1   (OFF_W2 + 64 * PW2P * 2)
#define OFF_B2   (OFF_B1 + 128)
#define SMEM_FLOATS (OFF_B2 + 64)
#define SMEM_BYTES  (SMEM_FLOATS * 4)       // 139,008 B -> 1 CTA/SM

// ---------------------------------------------------------------------------
// Helpers (no sm_103a-only instructions)
// ---------------------------------------------------------------------------
static __device__ __forceinline__ uint32_t f2tf(float f) {
    uint32_t u;
    asm("cvt.rna.tf32.f32 %0, %1;" : "=r"(u) : "f"(f));
    return u;
}
static __device__ __forceinline__ float rna_tf32(float f) {
    return __uint_as_float(f2tf(f));
}
// D += A(16x8) * B(8x8), tf32, row.col
static __device__ __forceinline__ void mma8(float* d, const uint32_t* a,
                                            uint32_t b0, uint32_t b1) {
    asm volatile(
        "mma.sync.aligned.m16n8k8.row.col.f32.tf32.tf32.f32 "
        "{%0,%1,%2,%3},{%4,%5,%6,%7},{%8,%9},{%0,%1,%2,%3};"
        : "+f"(d[0]), "+f"(d[1]), "+f"(d[2]), "+f"(d[3])
        : "r"(a[0]), "r"(a[1]), "r"(a[2]), "r"(a[3]), "r"(b0), "r"(b1));
}

// ---------------------------------------------------------------------------
// Layer kernel. Grid: (32 batch tiles, 64 blocks), 256 threads, 8 warps.
// Each warp owns 32 batch rows (2 m-tiles) x ALL columns. e-blocks processed
// in PAIRS -> 4 independent MMA chains in GEMM1 (ILP fix for latency bound).
// ---------------------------------------------------------------------------
template <int LAYER>
__global__ void __launch_bounds__(THR, 1)
layer_kernel(const float* __restrict__ x,
             const float* __restrict__ w1g, const float* __restrict__ b1g,
             const float* __restrict__ w2g, const float* __restrict__ b2g) {
    extern __shared__ float sm[];
    float*  sA   = sm + OFF_A;
    float2* sW1p = (float2*)(sm + OFF_W1);
    float2* sW2p = (float2*)(sm + OFF_W2);
    float*  sb1  = sm + OFF_B1;
    float*  sb2  = sm + OFF_B2;

    const int t    = threadIdx.x;
    const int wid  = t >> 5;
    const int lane = t & 31;
    const int g    = lane >> 2;     // groupID (0..7)
    const int tig  = lane & 3;      // thread-in-group (0..3)
    const int blk  = blockIdx.y;
    const int b0   = blockIdx.x * MT;
    const int ln   = LAYER * 64 + blk;

    // ---- biases
    if (t < 128)      sb1[t]       = b1g[(size_t)ln * 128 + t];
    else if (t < 192) sb2[t - 128] = b2g[(size_t)ln * 64 + (t - 128)];

    // ---- W1 [k=64][e=128] -> paired-k float2 sW1p[p=kt*4+tig'][e]
    {
        const float4* src = (const float4*)(w1g + (size_t)ln * 8192);
#pragma unroll
        for (int i = 0; i < 4; i++) {
            int idx = i * THR + t;          // 1024 = 32 p x 32 e4
            int p = idx >> 5, e4 = idx & 31;
            int klo = (p >> 2) * 8 + (p & 3);
            float4 vlo = src[klo * 32 + e4];
            float4 vhi = src[(klo + 4) * 32 + e4];
            float2* dst = sW1p + p * PW1P + e4 * 4;
            dst[0] = make_float2(rna_tf32(vlo.x), rna_tf32(vhi.x));
            dst[1] = make_float2(rna_tf32(vlo.y), rna_tf32(vhi.y));
            dst[2] = make_float2(rna_tf32(vlo.z), rna_tf32(vhi.z));
            dst[3] = make_float2(rna_tf32(vlo.w), rna_tf32(vhi.w));
        }
    }
    // ---- W2 [k=128][d=64] -> paired-k float2 sW2p[p=kb*4+tig'][d]
    {
        const float4* src = (const float4*)(w2g + (size_t)ln * 8192);
#pragma unroll
        for (int i = 0; i < 4; i++) {
            int idx = i * THR + t;          // 1024 = 64 p x 16 d4
            int p = idx >> 4, d4 = idx & 15;
            int klo = (p >> 2) * 8 + (p & 3);
            float4 vlo = src[klo * 16 + d4];
            float4 vhi = src[(klo + 4) * 16 + d4];
            float2* dst = sW2p + p * PW2P + d4 * 4;
            dst[0] = make_float2(rna_tf32(vlo.x), rna_tf32(vhi.x));
            dst[1] = make_float2(rna_tf32(vlo.y), rna_tf32(vhi.y));
            dst[2] = make_float2(rna_tf32(vlo.z), rna_tf32(vhi.z));
            dst[3] = make_float2(rna_tf32(vlo.w), rna_tf32(vhi.w));
        }
    }
    // ---- A tile (EXACT values; rounded at fragment load)
    if (LAYER == 0) {
#pragma unroll
        for (int i = 0; i < 16; i++) {
            int idx = i * THR + t;          // 4096 float4 = 256 b x 16 k4
            int b = idx >> 4, k4 = idx & 15;
            float4 v = *(const float4*)(x + (size_t)(b0 + b) * 4096 + blk * 64 + k4 * 4);
            *(float4*)(sA + b * PAB + k4 * 4) = v;
        }
    } else {
#pragma unroll
        for (int i = 0; i < 16; i++) {
            int idx = i * THR + t;          // 4096 float4 = 64 k x 64 b4
            int k = idx >> 6, b4 = idx & 63;
            float4 v = *(const float4*)(g_S + ((size_t)blk * 64 + k) * BSZ + b0 + b4 * 4);
            *(float4*)(sA + k * PAK + b4 * 4) = v;
        }
    }
    __syncthreads();
    // ======= from here on: warps fully independent =======

    const int m0  = wid * 32;               // this warp's 32-row band
    const int r0a = m0 + g;                 // m-tile 0: rows r0a, r0a+8
    const int r0b = m0 + 16 + g;            // m-tile 1: rows r0b, r0b+8

    // ---- GEMM1 A-fragments (rounded once): au[mt][kt][4]
    uint32_t au[2][8][4];
#pragma unroll
    for (int kt = 0; kt < 8; kt++) {
        int k = kt * 8 + tig;
        if (LAYER == 0) {
            au[0][kt][0] = f2tf(sA[r0a * PAB + k]);
            au[0][kt][1] = f2tf(sA[(r0a + 8) * PAB + k]);
            au[0][kt][2] = f2tf(sA[r0a * PAB + k + 4]);
            au[0][kt][3] = f2tf(sA[(r0a + 8) * PAB + k + 4]);
            au[1][kt][0] = f2tf(sA[r0b * PAB + k]);
            au[1][kt][1] = f2tf(sA[(r0b + 8) * PAB + k]);
            au[1][kt][2] = f2tf(sA[r0b * PAB + k + 4]);
            au[1][kt][3] = f2tf(sA[(r0b + 8) * PAB + k + 4]);
        } else {
            au[0][kt][0] = f2tf(sA[k * PAK + r0a]);
            au[0][kt][1] = f2tf(sA[k * PAK + r0a + 8]);
            au[0][kt][2] = f2tf(sA[(k + 4) * PAK + r0a]);
            au[0][kt][3] = f2tf(sA[(k + 4) * PAK + r0a + 8]);
            au[1][kt][0] = f2tf(sA[k * PAK + r0b]);
            au[1][kt][1] = f2tf(sA[k * PAK + r0b + 8]);
            au[1][kt][2] = f2tf(sA[(k + 4) * PAK + r0b]);
            au[1][kt][3] = f2tf(sA[(k + 4) * PAK + r0b + 8]);
        }
    }

    // ---- Fused GEMM1 -> ELU -> GEMM2 over 8 PAIRS of e-blocks
    float acc2[2][8][4];
#pragma unroll
    for (int mt = 0; mt < 2; mt++)
#pragma unroll
        for (int nt = 0; nt < 8; nt++)
#pragma unroll
            for (int c = 0; c < 4; c++) acc2[mt][nt][c] = 0.f;

    const int qbase = lane & ~3;            // quad base lane
    const int s0 = qbase | (tig >> 1);      // src lane for col tig
    const int s2 = s0 | 2;                  // src lane for col tig+4
    const bool odd = (tig & 1);

#pragma unroll
    for (int kb = 0; kb < 16; kb += 2) {
        // GEMM1 slice: C1[32 x 16] for e-blocks kb, kb+1
        // 4 independent accumulator chains (2 mt x 2 kb)
        float a1[2][2][4];
#pragma unroll
        for (int mt = 0; mt < 2; mt++)
#pragma unroll
            for (int q = 0; q < 2; q++)
#pragma unroll
                for (int c = 0; c < 4; c++) a1[mt][q][c] = 0.f;

#pragma unroll
        for (int kt = 0; kt < 8; kt++) {
            const float2* wrow = sW1p + (kt * 4 + tig) * PW1P;
            float2 wa = wrow[kb * 8 + g];
            float2 wb = wrow[kb * 8 + 8 + g];
            uint32_t wa0 = __float_as_uint(wa.x), wa1 = __float_as_uint(wa.y);
            uint32_t wb0 = __float_as_uint(wb.x), wb1 = __float_as_uint(wb.y);
            mma8(a1[0][0], au[0][kt], wa0, wa1);
            mma8(a1[1][0], au[1][kt], wa0, wa1);
            mma8(a1[0][1], au[0][kt], wb0, wb1);
            mma8(a1[1][1], au[1][kt], wb0, wb1);
        }

        // bias + ELU + round + quad-shuffle C-frag -> A-frag, both kb, both mt
        uint32_t a2f[2][2][4];
#pragma unroll
        for (int q = 0; q < 2; q++) {
            float bb0 = sb1[(kb + q) * 8 + tig * 2];
            float bb1 = sb1[(kb + q) * 8 + tig * 2 + 1];
#pragma unroll
            for (int mt = 0; mt < 2; mt++) {
                float h0 = a1[mt][q][0] + bb0;   // (r,   2tig)
                float h1 = a1[mt][q][1] + bb1;   // (r,   2tig+1)
                float h2 = a1[mt][q][2] + bb0;   // (r+8, 2tig)
                float h3 = a1[mt][q][3] + bb1;   // (r+8, 2tig+1)
                h0 = rna_tf32(h0 > 0.f ? h0 : (__expf(h0) - 1.f));
                h1 = rna_tf32(h1 > 0.f ? h1 : (__expf(h1) - 1.f));
                h2 = rna_tf32(h2 > 0.f ? h2 : (__expf(h2) - 1.f));
                h3 = rna_tf32(h3 > 0.f ? h3 : (__expf(h3) - 1.f));

                float p0 = __shfl_sync(0xffffffffu, h0, s0);
                float p1 = __shfl_sync(0xffffffffu, h1, s0);
                float q0 = __shfl_sync(0xffffffffu, h2, s0);
                float q1 = __shfl_sync(0xffffffffu, h3, s0);
                float r0f = __shfl_sync(0xffffffffu, h0, s2);
                float r1f = __shfl_sync(0xffffffffu, h1, s2);
                float u0 = __shfl_sync(0xffffffffu, h2, s2);
                float u1 = __shfl_sync(0xffffffffu, h3, s2);
                a2f[mt][q][0] = __float_as_uint(odd ? p1 : p0);   // (r,   tig)
                a2f[mt][q][1] = __float_as_uint(odd ? q1 : q0);   // (r+8, tig)
                a2f[mt][q][2] = __float_as_uint(odd ? r1f : r0f); // (r,   tig+4)
                a2f[mt][q][3] = __float_as_uint(odd ? u1 : u0);   // (r+8, tig+4)
            }
        }

        // GEMM2 accumulate: k-blocks kb, kb+1 (kb first, then kb+1 -> same
        // accumulation order as before => bitwise-identical result)
#pragma unroll
        for (int nt = 0; nt < 8; nt++) {
            const float2* w2row0 = sW2p + (kb * 4 + tig) * PW2P;
            const float2* w2row1 = sW2p + ((kb + 1) * 4 + tig) * PW2P;
            float2 w0p = w2row0[nt * 8 + g];
            float2 w1p = w2row1[nt * 8 + g];
            uint32_t wa0 = __float_as_uint(w0p.x), wa1 = __float_as_uint(w0p.y);
            uint32_t wb0 = __float_as_uint(w1p.x), wb1 = __float_as_uint(w1p.y);
            mma8(acc2[0][nt], a2f[0][0], wa0, wa1);
            mma8(acc2[1][nt], a2f[1][0], wa0, wa1);
            mma8(acc2[0][nt], a2f[0][1], wb0, wb1);
            mma8(acc2[1][nt], a2f[1][1], wb0, wb1);
        }
    }

    // ---- Epilogue: bias + residual (exact z from sA) + stores
#pragma unroll
    for (int mt = 0; mt < 2; mt++) {
        const int rbase = m0 + mt * 16 + g;
#pragma unroll
        for (int nt = 0; nt < 8; nt++) {
#pragma unroll
            for (int c = 0; c < 4; c++) {
                int row = rbase + 8 * (c >> 1);
                int d   = nt * 8 + tig * 2 + (c & 1);
                float z = (LAYER == 0) ? sA[row * PAB + d] : sA[d * PAK + row];
                float v = acc2[mt][nt][c] + sb2[d] + z;
                if (LAYER == 0)
                    g_S [((size_t)d * 64 + blk) * BSZ + b0 + row] = v;   // [d][m=blk][b]
                else
                    g_S2[((size_t)d * 64 + blk) * BSZ + b0 + row] = v;   // [f][b]
            }
        }
    }
}

// ---------------------------------------------------------------------------
// Final transpose: out[b][f] = g_S2[f][b]   (4096 x 8192 -> 8192 x 4096)
// ---------------------------------------------------------------------------
__global__ void __launch_bounds__(256)
transpose_kernel(float* __restrict__ out) {
    __shared__ float tile[64 * 68];
    const int f0 = blockIdx.x * 64, bb0 = blockIdx.y * 64;
    const int t = threadIdx.x;
#pragma unroll
    for (int p = 0; p < 4; p++) {
        int idx = p * 256 + t;              // 1024 float4 = 64 f x 16 b4
        int f = idx >> 4, b4 = idx & 15;
        float4 v = *(const float4*)(g_S2 + (size_t)(f0 + f) * BSZ + bb0 + b4 * 4);
        float* d = tile + f * 68 + b4 * 4;
        d[0] = v.x; d[1] = v.y; d[2] = v.z; d[3] = v.w;
    }
    __syncthreads();
#pragma unroll
    for (int p = 0; p < 4; p++) {
        int idx = p * 256 + t;              // 1024 float4 = 64 b x 16 f4
        int b = idx >> 4, f4 = idx & 15;
        float4 v;
        v.x = tile[(f4 * 4 + 0) * 68 + b];
        v.y = tile[(f4 * 4 + 1) * 68 + b];
        v.z = tile[(f4 * 4 + 2) * 68 + b];
        v.w = tile[(f4 * 4 + 3) * 68 + b];
        *(float4*)(out + (size_t)(bb0 + b) * 4096 + f0 + f4 * 4) = v;
    }
}

// ---------------------------------------------------------------------------
// kernel_launch
// ---------------------------------------------------------------------------
extern "C" void kernel_launch(void* const* d_in, const int* in_sizes, int n_in,
                              void* d_out, int out_size) {
    const float* x  = (const float*)d_in[0];
    const float* w1 = (const float*)d_in[1];
    const float* b1 = (const float*)d_in[2];
    const float* w2 = (const float*)d_in[3];
    const float* b2 = (const float*)d_in[4];
    float* out = (float*)d_out;
    (void)in_sizes; (void)n_in; (void)out_size;

    cudaFuncSetAttribute(layer_kernel<0>, cudaFuncAttributeMaxDynamicSharedMemorySize, SMEM_BYTES);
    cudaFuncSetAttribute(layer_kernel<1>, cudaFuncAttributeMaxDynamicSharedMemorySize, SMEM_BYTES);

    layer_kernel<0><<<dim3(32, 64), THR, SMEM_BYTES>>>(x, w1, b1, w2, b2);
    layer_kernel<1><<<dim3(32, 64), THR, SMEM_BYTES>>>(x, w1, b1, w2, b2);
    transpose_kernel<<<dim3(64, 128), 256>>>(out);
}